// round 8
// baseline (speedup 1.0000x reference)
#include <cuda_runtime.h>
#include <cuda_bf16.h>
#include <cstdint>
#include <math.h>

// Problem constants
#define BB 2
#define SS 2048
#define EE 2048
#define HH 16
#define DD 128
#define MROWS (BB * SS)          // 4096
#define QKV_N (3 * EE)           // 6144

// ---------------- scratch (device globals: allocation-free) ----------------
__device__ __nv_bfloat16 g_xh [(size_t)MROWS * EE];
__device__ __nv_bfloat16 g_xl [(size_t)MROWS * EE];
__device__ __nv_bfloat16 g_wqh[(size_t)QKV_N * EE];
__device__ __nv_bfloat16 g_wql[(size_t)QKV_N * EE];
__device__ __nv_bfloat16 g_woh[(size_t)EE * EE];
__device__ __nv_bfloat16 g_wol[(size_t)EE * EE];
__device__ float g_qkv [(size_t)MROWS * QKV_N];         // [4096, 6144] fp32
__device__ float g_Q   [(size_t)BB * HH * SS * DD];     // [b,h,s,d] (roped)
__device__ float g_K   [(size_t)BB * HH * SS * DD];     // [b,h,s,d] (roped)
__device__ float g_Vt  [(size_t)BB * HH * DD * SS];     // [b,h,d,s]
__device__ __nv_bfloat16 g_yh [(size_t)MROWS * EE];     // attn out hi
__device__ __nv_bfloat16 g_yl [(size_t)MROWS * EE];     // attn out lo

// ======================= helpers ===========================================
__device__ __forceinline__ uint32_t smem_u32(const void* p) {
    uint32_t a;
    asm("{ .reg .u64 t; cvta.to.shared.u64 t, %1; cvt.u32.u64 %0, t; }"
        : "=r"(a) : "l"(p));
    return a;
}

__device__ __forceinline__ float to_tf32(float x) {
    uint32_t u;
    asm("cvt.rna.tf32.f32 %0, %1;" : "=r"(u) : "f"(x));
    return __uint_as_float(u);
}

__device__ __forceinline__ float4 round4(float4 v) {
    v.x = to_tf32(v.x); v.y = to_tf32(v.y);
    v.z = to_tf32(v.z); v.w = to_tf32(v.w);
    return v;
}

// split two floats into packed bf16 hi pair (ret) and lo pair (out param)
__device__ __forceinline__ uint32_t split2(float a, float b, uint32_t& lo) {
    __nv_bfloat16 ha = __float2bfloat16_rn(a), hb = __float2bfloat16_rn(b);
    __nv_bfloat16 la = __float2bfloat16_rn(a - __bfloat162float(ha));
    __nv_bfloat16 lb = __float2bfloat16_rn(b - __bfloat162float(hb));
    uint16_t uha = *(uint16_t*)&ha, uhb = *(uint16_t*)&hb;
    uint16_t ula = *(uint16_t*)&la, ulb = *(uint16_t*)&lb;
    lo = (uint32_t)ula | ((uint32_t)ulb << 16);
    return (uint32_t)uha | ((uint32_t)uhb << 16);
}

#define CPA16(dst, src) \
    asm volatile("cp.async.cg.shared.global [%0], [%1], 16;" :: "r"(dst), "l"(src))
#define CPA_COMMIT()  asm volatile("cp.async.commit_group;" ::: "memory")
#define CPA_WAIT1()   asm volatile("cp.async.wait_group 1;" ::: "memory")

#define LDSM4(r, addr)                                                        \
    asm volatile("ldmatrix.sync.aligned.m8n8.x4.shared.b16 {%0,%1,%2,%3}, [%4];" \
        : "=r"((r)[0]), "=r"((r)[1]), "=r"((r)[2]), "=r"((r)[3]) : "r"(addr))

#define MMA_TF32(c, a, b0, b1)                                                \
    asm volatile("mma.sync.aligned.m16n8k8.row.col.f32.tf32.tf32.f32 "        \
        "{%0,%1,%2,%3}, {%4,%5,%6,%7}, {%8,%9}, {%0,%1,%2,%3};"               \
        : "+f"((c)[0]), "+f"((c)[1]), "+f"((c)[2]), "+f"((c)[3])              \
        : "r"((a)[0]), "r"((a)[1]), "r"((a)[2]), "r"((a)[3]), "r"(b0), "r"(b1))

#define MMA_BF16(c, a, b0, b1)                                                \
    asm volatile("mma.sync.aligned.m16n8k16.row.col.f32.bf16.bf16.f32 "       \
        "{%0,%1,%2,%3}, {%4,%5,%6,%7}, {%8,%9}, {%0,%1,%2,%3};"               \
        : "+f"((c)[0]), "+f"((c)[1]), "+f"((c)[2]), "+f"((c)[3])              \
        : "r"((a)[0]), "r"((a)[1]), "r"((a)[2]), "r"((a)[3]), "r"(b0), "r"(b1))

// ======= split-bf16 GEMM: C[M,N] = A[M,K] @ B[N,K]^T  (hi/lo planes) =======
// CTA 128x128, 256 thr / 8 warps (4m x 2n), warptile 32x64, 3-stage cp.async.
// SMEM row layout per matrix row: [k0..31 hi][k0..31 lo][8 pad] bf16 (pitch 72).
#define BP 72                                // b16 pitch -> 144 B row stride
#define BOFF (128 * BP * 2)                  // B region offset in stage (bytes)
#define STG_B (256 * BP * 2)                 // 36864 bytes
#define GEMM_SMEM (3 * STG_B)                // 110592 bytes

__device__ __forceinline__ void g2s_stage(const __nv_bfloat16* Ah, const __nv_bfloat16* Al,
                                          const __nv_bfloat16* Bh, const __nv_bfloat16* Bl,
                                          int K, uint32_t stg, int tid) {
#pragma unroll
    for (int j = 0; j < 4; j++) {            // A: 128 rows x 8 chunks of 16B
        int cid = tid + j * 256;
        int row = cid >> 3, chk = cid & 7;
        const __nv_bfloat16* src = (chk < 4) ? (Ah + (size_t)row * K + chk * 8)
                                             : (Al + (size_t)row * K + (chk - 4) * 8);
        CPA16(stg + (uint32_t)(row * 144 + chk * 16), src);
    }
#pragma unroll
    for (int j = 0; j < 4; j++) {            // B: 128 rows x 8 chunks
        int cid = tid + j * 256;
        int row = cid >> 3, chk = cid & 7;
        const __nv_bfloat16* src = (chk < 4) ? (Bh + (size_t)row * K + chk * 8)
                                             : (Bl + (size_t)row * K + (chk - 4) * 8);
        CPA16(stg + BOFF + (uint32_t)(row * 144 + chk * 16), src);
    }
}

__global__ __launch_bounds__(256, 2)
void gemm_mma(const __nv_bfloat16* __restrict__ Ah, const __nv_bfloat16* __restrict__ Al,
              const __nv_bfloat16* __restrict__ Bh, const __nv_bfloat16* __restrict__ Bl,
              float* __restrict__ C, int N, int K) {
    extern __shared__ char smem[];
    const uint32_t sbase = smem_u32(smem);
    const int tid  = threadIdx.x;
    const int wid  = tid >> 5;
    const int lane = tid & 31;
    const int wm   = wid >> 1;               // 0..3 (32 rows)
    const int wn   = wid & 1;                // 0..1 (64 cols)
    const int m0 = blockIdx.y * 128;
    const int n0 = blockIdx.x * 128;
    const int iters = K >> 5;

    const __nv_bfloat16* Abh = Ah + (size_t)m0 * K;
    const __nv_bfloat16* Abl = Al + (size_t)m0 * K;
    const __nv_bfloat16* Bbh = Bh + (size_t)n0 * K;
    const __nv_bfloat16* Bbl = Bl + (size_t)n0 * K;

    float c[2][8][4];
#pragma unroll
    for (int i = 0; i < 2; i++)
#pragma unroll
        for (int j = 0; j < 8; j++)
#pragma unroll
            for (int q = 0; q < 4; q++) c[i][j][q] = 0.f;

    const int sub = lane >> 3;
    const int r8  = lane & 7;
    // A mats: (r0-7,k0-7),(r8-15,k0-7),(r0-7,k8-15),(r8-15,k8-15) -> a0..a3
    const uint32_t aoff = (uint32_t)((wm * 32 + (sub & 1) * 8 + r8) * BP + (sub >> 1) * 8) * 2;
    // B mats: (n0-7,k0-7),(n0-7,k8-15),(n8-15,k0-7),(n8-15,k8-15)
    const uint32_t boff = BOFF + (uint32_t)((wn * 64 + (sub >> 1) * 8 + r8) * BP + (sub & 1) * 8) * 2;

    g2s_stage(Abh, Abl, Bbh, Bbl, K, sbase, tid);                         CPA_COMMIT();
    g2s_stage(Abh + 32, Abl + 32, Bbh + 32, Bbl + 32, K, sbase + STG_B, tid); CPA_COMMIT();

    for (int i = 0; i < iters; i++) {
        CPA_WAIT1();
        __syncthreads();
        if (i + 2 < iters) {
            uint32_t stg = sbase + (uint32_t)((i + 2) % 3) * STG_B;
            g2s_stage(Abh + (i + 2) * 32, Abl + (i + 2) * 32,
                      Bbh + (i + 2) * 32, Bbl + (i + 2) * 32, K, stg, tid);
            CPA_COMMIT();
        }
        const uint32_t ab = sbase + (uint32_t)(i % 3) * STG_B + aoff;
        const uint32_t bb = sbase + (uint32_t)(i % 3) * STG_B + boff;

#pragma unroll
        for (int kk = 0; kk < 2; kk++) {     // two k16 steps per 32-K chunk
            uint32_t ah[2][4], al[2][4], b[4][4];
#pragma unroll
            for (int im = 0; im < 2; im++)
                LDSM4(ah[im], ab + (uint32_t)(im * 16 * BP) * 2 + kk * 32);
#pragma unroll
            for (int im = 0; im < 2; im++)
                LDSM4(al[im], ab + (uint32_t)(im * 16 * BP) * 2 + kk * 32 + 64);
#pragma unroll
            for (int nt = 0; nt < 4; nt++)   // B hi
                LDSM4(b[nt], bb + (uint32_t)(nt * 16 * BP) * 2 + kk * 32);
            // hi*hi
#pragma unroll
            for (int im = 0; im < 2; im++)
#pragma unroll
                for (int jn = 0; jn < 8; jn++)
                    MMA_BF16(c[im][jn], ah[im],
                             b[jn >> 1][(jn & 1) * 2], b[jn >> 1][(jn & 1) * 2 + 1]);
            // lo*hi
#pragma unroll
            for (int im = 0; im < 2; im++)
#pragma unroll
                for (int jn = 0; jn < 8; jn++)
                    MMA_BF16(c[im][jn], al[im],
                             b[jn >> 1][(jn & 1) * 2], b[jn >> 1][(jn & 1) * 2 + 1]);
            // reload B lo, hi*lo
#pragma unroll
            for (int nt = 0; nt < 4; nt++)
                LDSM4(b[nt], bb + (uint32_t)(nt * 16 * BP) * 2 + kk * 32 + 64);
#pragma unroll
            for (int im = 0; im < 2; im++)
#pragma unroll
                for (int jn = 0; jn < 8; jn++)
                    MMA_BF16(c[im][jn], ah[im],
                             b[jn >> 1][(jn & 1) * 2], b[jn >> 1][(jn & 1) * 2 + 1]);
        }
    }

    const int g = lane >> 2, q = lane & 3;
#pragma unroll
    for (int im = 0; im < 2; im++)
#pragma unroll
        for (int jn = 0; jn < 8; jn++) {
            int row = m0 + wm * 32 + im * 16 + g;
            int col = n0 + wn * 64 + jn * 8 + q * 2;
            *(float2*)&C[(size_t)row * N + col]       = make_float2(c[im][jn][0], c[im][jn][1]);
            *(float2*)&C[(size_t)(row + 8) * N + col] = make_float2(c[im][jn][2], c[im][jn][3]);
        }
}

// ---------------- fp32 -> bf16 hi/lo split ---------------------------------
__global__ void split_bf16_k(const float4* __restrict__ in,
                             uint4* __restrict__ hip, uint4* __restrict__ lop, int n8) {
    int i = blockIdx.x * blockDim.x + threadIdx.x;
    if (i >= n8) return;
    float4 a = in[2 * i], b = in[2 * i + 1];
    uint4 H, L;
    H.x = split2(a.x, a.y, L.x);
    H.y = split2(a.z, a.w, L.y);
    H.z = split2(b.x, b.y, L.z);
    H.w = split2(b.z, b.w, L.w);
    hip[i] = H;
    lop[i] = L;
}

// ---------------- RoPE for Q,K → [b,h,s,d] ---------------------------------
__global__ void rope_qk(const float* __restrict__ qkv,
                        float* __restrict__ Q, float* __restrict__ K) {
    int idx = blockIdx.x * blockDim.x + threadIdx.x;
    int d  = idx & 127;
    int s  = (idx >> 7) & 2047;
    int bh = idx >> 18;
    int i  = d & 63;
    float theta = (float)s * exp2f(-0.20762050593045998f * (float)i);
    float sn, cs;
    sincosf(theta, &sn, &cs);
    const float* row = qkv + (size_t)((bh >> 4) * 2048 + s) * QKV_N;
    int nq = (bh & 15) * 128;
    float qv = row[nq + d];
    float qp = row[nq + (d ^ 64)];
    float kv = row[2048 + nq + d];
    float kp = row[2048 + nq + (d ^ 64)];
    float qr = (d < 64) ? -qp : qp;
    float kr = (d < 64) ? -kp : kp;
    Q[idx] = qv * cs + qr * sn;
    K[idx] = kv * cs + kr * sn;
}

// ---------------- V transpose → [b,h,d,s] ----------------------------------
__global__ void transpose_v(const float* __restrict__ qkv, float* __restrict__ Vt) {
    __shared__ float t[32][33];
    int bh = blockIdx.z;
    int b = bh >> 4, h = bh & 15;
    int s0 = blockIdx.x * 32, d0 = blockIdx.y * 32;
    int tx = threadIdx.x, ty = threadIdx.y;
    const float* src = qkv + ((size_t)(b * SS + s0 + ty)) * QKV_N + 4096 + h * 128 + d0 + tx;
#pragma unroll
    for (int j = 0; j < 32; j += 8)
        t[ty + j][tx] = src[(size_t)j * QKV_N];
    __syncthreads();
    float* dst = Vt + ((size_t)bh * DD + d0 + ty) * SS + s0 + tx;
#pragma unroll
    for (int j = 0; j < 32; j += 8)
        dst[(size_t)j * SS] = t[tx][ty + j];
}

// ---------------- Flash attention via mma.sync tf32 ------------------------
#define QP 132                               // pitch (floats) for Qs/Ks
#define PP 68                                // pitch for Vs/Ps
#define ATTN2_SMEM ((128 * QP + 64 * QP + 128 * PP + 128 * PP) * 4)

__global__ __launch_bounds__(256, 1)
void attn_mma(const float* __restrict__ Qg_, const float* __restrict__ Kg_,
              const float* __restrict__ Vt_,
              __nv_bfloat16* __restrict__ Yh, __nv_bfloat16* __restrict__ Yl) {
    extern __shared__ float sm[];
    float* Qs = sm;                          // [128][QP]  rows=qrow cols=d
    float* Ks = Qs + 128 * QP;               // [64][QP]   rows=kcol cols=d
    float* Vs = Ks + 64 * QP;                // [128][PP]  rows=d    cols=kcol
    float* Ps = Vs + 128 * PP;               // [128][PP]  rows=qrow cols=kcol

    const int tid  = threadIdx.x;
    const int wid  = tid >> 5;
    const int lane = tid & 31;
    const int qb = gridDim.x - 1 - blockIdx.x;
    const int h  = blockIdx.y;
    const int b  = blockIdx.z;
    const int q0 = qb * 128;

    const size_t bh = (size_t)(b * HH + h);
    const float* Qg = Qg_ + bh * SS * DD;
    const float* Kg = Kg_ + bh * SS * DD;
    const float* Vg = Vt_ + bh * DD * SS;

    const float scale = 0.088388347648318447f;
#pragma unroll
    for (int p = 0; p < 16; p++) {
        int idx = tid + p * 256;
        int row = idx >> 5, ch = idx & 31;
        float4 v = *(const float4*)&Qg[(size_t)(q0 + row) * DD + ch * 4];
        v.x *= scale; v.y *= scale; v.z *= scale; v.w *= scale;
        *(float4*)&Qs[row * QP + ch * 4] = round4(v);
    }

    const int sub = lane >> 3, r8 = lane & 7;
    const int g = lane >> 2, qq = lane & 3;
    const uint32_t a_q = smem_u32(Qs) + (uint32_t)((wid * 16 + (sub & 1) * 8 + r8) * QP + (sub >> 1) * 4) * 4;
    const uint32_t b_k = smem_u32(Ks) + (uint32_t)(((sub >> 1) * 8 + r8) * QP + (sub & 1) * 4) * 4;
    const uint32_t a_p = smem_u32(Ps) + (uint32_t)((wid * 16 + (sub & 1) * 8 + r8) * PP + (sub >> 1) * 4) * 4;
    const uint32_t b_v = smem_u32(Vs) + (uint32_t)(((sub >> 1) * 8 + r8) * PP + (sub & 1) * 4) * 4;

    float o[16][4];
#pragma unroll
    for (int i = 0; i < 16; i++)
#pragma unroll
        for (int j = 0; j < 4; j++) o[i][j] = 0.f;
    float m0v = -1e30f, m1v = -1e30f, l0 = 0.f, l1 = 0.f;

    const int nkt = 2 * qb + 2;
    for (int kt = 0; kt < nkt; kt++) {
        const int k0 = kt * 64;
        __syncthreads();
#pragma unroll
        for (int p = 0; p < 8; p++) {
            int idx = tid + p * 256;
            int row = idx >> 5, ch = idx & 31;
            *(float4*)&Ks[row * QP + ch * 4] =
                round4(*(const float4*)&Kg[(size_t)(k0 + row) * DD + ch * 4]);
        }
#pragma unroll
        for (int p = 0; p < 8; p++) {
            int idx = tid + p * 256;
            int row = idx >> 4, ch = idx & 15;
            *(float4*)&Vs[row * PP + ch * 4] =
                round4(*(const float4*)&Vg[(size_t)row * SS + k0 + ch * 4]);
        }
        __syncthreads();

        float s[8][4];
#pragma unroll
        for (int i = 0; i < 8; i++)
#pragma unroll
            for (int j = 0; j < 4; j++) s[i][j] = 0.f;
#pragma unroll
        for (int kd = 0; kd < 16; kd++) {
            uint32_t a[4];
            LDSM4(a, a_q + kd * 32);
            uint32_t bf[4][4];
#pragma unroll
            for (int nt = 0; nt < 4; nt++)
                LDSM4(bf[nt], b_k + (uint32_t)(nt * 16 * QP) * 4 + kd * 32);
#pragma unroll
            for (int nt = 0; nt < 4; nt++) {
                MMA_TF32(s[nt * 2],     a, bf[nt][0], bf[nt][1]);
                MMA_TF32(s[nt * 2 + 1], a, bf[nt][2], bf[nt][3]);
            }
        }

        if (kt >= 2 * qb) {
            int row0 = q0 + wid * 16 + g;
#pragma unroll
            for (int j = 0; j < 8; j++) {
                int c = k0 + j * 8 + qq * 2;
                if (c     > row0)     s[j][0] = -1e30f;
                if (c + 1 > row0)     s[j][1] = -1e30f;
                if (c     > row0 + 8) s[j][2] = -1e30f;
                if (c + 1 > row0 + 8) s[j][3] = -1e30f;
            }
        }

        float tm0 = -1e30f, tm1 = -1e30f;
#pragma unroll
        for (int j = 0; j < 8; j++) {
            tm0 = fmaxf(tm0, fmaxf(s[j][0], s[j][1]));
            tm1 = fmaxf(tm1, fmaxf(s[j][2], s[j][3]));
        }
        tm0 = fmaxf(tm0, __shfl_xor_sync(0xffffffffu, tm0, 1));
        tm0 = fmaxf(tm0, __shfl_xor_sync(0xffffffffu, tm0, 2));
        tm1 = fmaxf(tm1, __shfl_xor_sync(0xffffffffu, tm1, 1));
        tm1 = fmaxf(tm1, __shfl_xor_sync(0xffffffffu, tm1, 2));
        float mn0 = fmaxf(m0v, tm0), mn1 = fmaxf(m1v, tm1);
        float al0 = __expf(m0v - mn0), al1 = __expf(m1v - mn1);
        m0v = mn0; m1v = mn1;
        float rs0 = 0.f, rs1 = 0.f;
#pragma unroll
        for (int j = 0; j < 8; j++) {
            s[j][0] = __expf(s[j][0] - mn0);
            s[j][1] = __expf(s[j][1] - mn0);
            s[j][2] = __expf(s[j][2] - mn1);
            s[j][3] = __expf(s[j][3] - mn1);
            rs0 += s[j][0] + s[j][1];
            rs1 += s[j][2] + s[j][3];
        }
        rs0 += __shfl_xor_sync(0xffffffffu, rs0, 1);
        rs0 += __shfl_xor_sync(0xffffffffu, rs0, 2);
        rs1 += __shfl_xor_sync(0xffffffffu, rs1, 1);
        rs1 += __shfl_xor_sync(0xffffffffu, rs1, 2);
        l0 = l0 * al0 + rs0;
        l1 = l1 * al1 + rs1;
#pragma unroll
        for (int nt = 0; nt < 16; nt++) {
            o[nt][0] *= al0; o[nt][1] *= al0;
            o[nt][2] *= al1; o[nt][3] *= al1;
        }

        {
            int pr0 = (wid * 16 + g) * PP;
#pragma unroll
            for (int j = 0; j < 8; j++) {
                *(float2*)&Ps[pr0 + j * 8 + qq * 2] =
                    make_float2(to_tf32(s[j][0]), to_tf32(s[j][1]));
                *(float2*)&Ps[pr0 + 8 * PP + j * 8 + qq * 2] =
                    make_float2(to_tf32(s[j][2]), to_tf32(s[j][3]));
            }
        }
        __syncwarp();

#pragma unroll
        for (int jk = 0; jk < 8; jk++) {
            uint32_t a[4];
            LDSM4(a, a_p + jk * 32);
#pragma unroll
            for (int nt = 0; nt < 8; nt++) {
                uint32_t bf[4];
                LDSM4(bf, b_v + (uint32_t)(nt * 16 * PP) * 4 + jk * 32);
                MMA_TF32(o[nt * 2],     a, bf[0], bf[1]);
                MMA_TF32(o[nt * 2 + 1], a, bf[2], bf[3]);
            }
        }
    }

    // normalize + bf16 hi/lo split + write Y planes [b,s,h,d]
    float i0 = 1.f / l0, i1 = 1.f / l1;
    int row0 = q0 + wid * 16 + g;
    size_t base0 = ((size_t)b * SS + row0) * EE + h * 128;
    size_t base1 = base0 + (size_t)8 * EE;
#pragma unroll
    for (int nt = 0; nt < 16; nt++) {
        int col = nt * 8 + qq * 2;
        uint32_t L0, L1;
        uint32_t H0 = split2(o[nt][0] * i0, o[nt][1] * i0, L0);
        uint32_t H1 = split2(o[nt][2] * i1, o[nt][3] * i1, L1);
        *(uint32_t*)&Yh[base0 + col] = H0;
        *(uint32_t*)&Yl[base0 + col] = L0;
        *(uint32_t*)&Yh[base1 + col] = H1;
        *(uint32_t*)&Yl[base1 + col] = L1;
    }
}

// ---------------- launch -----------------------------------------------------
extern "C" void kernel_launch(void* const* d_in, const int* in_sizes, int n_in,
                              void* d_out, int out_size) {
    const float* x     = (const float*)d_in[0];
    const float* w_qkv = (const float*)d_in[1];
    const float* w_out = (const float*)d_in[2];
    float* out = (float*)d_out;

    __nv_bfloat16 *p_xh, *p_xl, *p_wqh, *p_wql, *p_woh, *p_wol, *p_yh, *p_yl;
    float *p_qkv, *p_Q, *p_K, *p_Vt;
    cudaGetSymbolAddress((void**)&p_xh,  g_xh);
    cudaGetSymbolAddress((void**)&p_xl,  g_xl);
    cudaGetSymbolAddress((void**)&p_wqh, g_wqh);
    cudaGetSymbolAddress((void**)&p_wql, g_wql);
    cudaGetSymbolAddress((void**)&p_woh, g_woh);
    cudaGetSymbolAddress((void**)&p_wol, g_wol);
    cudaGetSymbolAddress((void**)&p_qkv, g_qkv);
    cudaGetSymbolAddress((void**)&p_Q,   g_Q);
    cudaGetSymbolAddress((void**)&p_K,   g_K);
    cudaGetSymbolAddress((void**)&p_Vt,  g_Vt);
    cudaGetSymbolAddress((void**)&p_yh,  g_yh);
    cudaGetSymbolAddress((void**)&p_yl,  g_yl);

    cudaFuncSetAttribute(gemm_mma, cudaFuncAttributeMaxDynamicSharedMemorySize, GEMM_SMEM);
    cudaFuncSetAttribute(attn_mma, cudaFuncAttributeMaxDynamicSharedMemorySize, ATTN2_SMEM);

    // 0) split GEMM operands into bf16 hi/lo planes
    split_bf16_k<<<(MROWS * EE / 8 + 255) / 256, 256>>>(
        (const float4*)x, (uint4*)p_xh, (uint4*)p_xl, MROWS * EE / 8);
    split_bf16_k<<<(QKV_N * EE / 8 + 255) / 256, 256>>>(
        (const float4*)w_qkv, (uint4*)p_wqh, (uint4*)p_wql, QKV_N * EE / 8);
    split_bf16_k<<<(EE * EE / 8 + 255) / 256, 256>>>(
        (const float4*)w_out, (uint4*)p_woh, (uint4*)p_wol, EE * EE / 8);

    // 1) qkv = x @ w_qkv^T  (split-bf16)
    gemm_mma<<<dim3(QKV_N / 128, MROWS / 128), 256, GEMM_SMEM>>>(
        p_xh, p_xl, p_wqh, p_wql, p_qkv, QKV_N, EE);
    // 2) RoPE → Q,K [b,h,s,d]; V transpose → [b,h,d,s]
    rope_qk<<<(BB * HH * SS * DD) / 256, 256>>>(p_qkv, p_Q, p_K);
    transpose_v<<<dim3(SS / 32, DD / 32, BB * HH), dim3(32, 8)>>>(p_qkv, p_Vt);
    // 3) flash attention (mma.sync tf32), emits y hi/lo bf16 planes
    attn_mma<<<dim3(SS / 128, HH, BB), 256, ATTN2_SMEM>>>(p_Q, p_K, p_Vt, p_yh, p_yl);
    // 4) out = y @ w_out^T  (split-bf16)
    gemm_mma<<<dim3(EE / 128, MROWS / 128), 256, GEMM_SMEM>>>(
        p_yh, p_yl, p_woh, p_wol, out, EE, EE);
}

// round 9
// speedup vs baseline: 1.2859x; 1.2859x over previous
#include <cuda_runtime.h>
#include <cuda_bf16.h>
#include <cstdint>
#include <math.h>

// Problem constants
#define BB 2
#define SS 2048
#define EE 2048
#define HH 16
#define DD 128
#define MROWS (BB * SS)          // 4096
#define QKV_N (3 * EE)           // 6144

// ---------------- scratch (device globals: allocation-free) ----------------
__device__ float g_x   [(size_t)MROWS * EE];            // tf32-rounded x
__device__ float g_wqkv[(size_t)QKV_N * EE];            // tf32-rounded w_qkv
__device__ float g_wout[(size_t)EE * EE];               // tf32-rounded w_out
__device__ float g_qkv [(size_t)MROWS * QKV_N];         // [4096, 6144] fp32
__device__ float g_Q   [(size_t)BB * HH * SS * DD];     // [b,h,s,d] roped, scaled, tf32
__device__ float g_K   [(size_t)BB * HH * SS * DD];     // [b,h,s,d] roped, tf32
__device__ float g_Vt  [(size_t)BB * HH * DD * SS];     // [b,h,d,s] tf32
__device__ float g_y   [(size_t)MROWS * EE];            // [b,s,h,d], tf32-rounded

// ======================= helpers ===========================================
__device__ __forceinline__ uint32_t smem_u32(const void* p) {
    uint32_t a;
    asm("{ .reg .u64 t; cvta.to.shared.u64 t, %1; cvt.u32.u64 %0, t; }"
        : "=r"(a) : "l"(p));
    return a;
}

__device__ __forceinline__ float to_tf32(float x) {
    uint32_t u;
    asm("cvt.rna.tf32.f32 %0, %1;" : "=r"(u) : "f"(x));
    return __uint_as_float(u);
}

__device__ __forceinline__ float4 round4(float4 v) {
    v.x = to_tf32(v.x); v.y = to_tf32(v.y);
    v.z = to_tf32(v.z); v.w = to_tf32(v.w);
    return v;
}

#define CPA16(dst, src) \
    asm volatile("cp.async.cg.shared.global [%0], [%1], 16;" :: "r"(dst), "l"(src))
#define CPA_COMMIT()  asm volatile("cp.async.commit_group;" ::: "memory")
#define CPA_WAIT1()   asm volatile("cp.async.wait_group 1;" ::: "memory")
#define CPA_WAIT0()   asm volatile("cp.async.wait_group 0;" ::: "memory")

#define LDSM4(r, addr)                                                        \
    asm volatile("ldmatrix.sync.aligned.m8n8.x4.shared.b16 {%0,%1,%2,%3}, [%4];" \
        : "=r"((r)[0]), "=r"((r)[1]), "=r"((r)[2]), "=r"((r)[3]) : "r"(addr))

#define MMA_TF32(c, a, b0, b1)                                                \
    asm volatile("mma.sync.aligned.m16n8k8.row.col.f32.tf32.tf32.f32 "        \
        "{%0,%1,%2,%3}, {%4,%5,%6,%7}, {%8,%9}, {%0,%1,%2,%3};"               \
        : "+f"((c)[0]), "+f"((c)[1]), "+f"((c)[2]), "+f"((c)[3])              \
        : "r"((a)[0]), "r"((a)[1]), "r"((a)[2]), "r"((a)[3]), "r"(b0), "r"(b1))

// ============ mma.sync tf32 GEMM: C[M,N] = A[M,K] @ B[N,K]^T ===============
// CTA 128x128, 256 thr / 8 warps (4m x 2n), warptile 32x64, 3-stage cp.async
// 2 CTAs per SM (110.6 KB SMEM each) to overlap barrier/wait phases.
#define GP 36                                // SMEM pitch (floats), %32==4
#define BOFF (128 * GP * 4)                  // B offset within stage (bytes)
#define STG_B ((128 + 128) * GP * 4)         // 36864 bytes
#define GEMM_SMEM (3 * STG_B)                // 110592 bytes

__device__ __forceinline__ void g2s_stage(const float* A, const float* B, int K,
                                          uint32_t stg, int tid) {
#pragma unroll
    for (int j = 0; j < 4; j++) {            // A: 128 rows x 8 chunks
        int cid = tid + j * 256;
        int row = cid >> 3, chk = cid & 7;
        CPA16(stg + (uint32_t)(row * GP + chk * 4) * 4,
              A + (size_t)row * K + chk * 4);
    }
#pragma unroll
    for (int j = 0; j < 4; j++) {            // B: 128 rows x 8 chunks
        int cid = tid + j * 256;
        int row = cid >> 3, chk = cid & 7;
        CPA16(stg + BOFF + (uint32_t)(row * GP + chk * 4) * 4,
              B + (size_t)row * K + chk * 4);
    }
}

__global__ __launch_bounds__(256, 2)
void gemm_mma(const float* __restrict__ A, const float* __restrict__ B,
              float* __restrict__ C, int N, int K) {
    extern __shared__ char smem[];
    const uint32_t sbase = smem_u32(smem);
    const int tid  = threadIdx.x;
    const int wid  = tid >> 5;
    const int lane = tid & 31;
    const int wm   = wid >> 1;               // 0..3 (32 rows)
    const int wn   = wid & 1;                // 0..1 (64 cols)
    const int m0 = blockIdx.y * 128;
    const int n0 = blockIdx.x * 128;
    const int iters = K >> 5;

    const float* Ab = A + (size_t)m0 * K;
    const float* Bb = B + (size_t)n0 * K;

    float c[2][8][4];
#pragma unroll
    for (int i = 0; i < 2; i++)
#pragma unroll
        for (int j = 0; j < 8; j++)
#pragma unroll
            for (int q = 0; q < 4; q++) c[i][j][q] = 0.f;

    const int sub = lane >> 3;
    const int r8  = lane & 7;
    const uint32_t aoff = (uint32_t)((wm * 32 + (sub & 1) * 8 + r8) * GP + (sub >> 1) * 4) * 4;
    const uint32_t boff = BOFF + (uint32_t)((wn * 64 + (sub >> 1) * 8 + r8) * GP + (sub & 1) * 4) * 4;

    g2s_stage(Ab, Bb, K, sbase, tid);                   CPA_COMMIT();
    g2s_stage(Ab + 32, Bb + 32, K, sbase + STG_B, tid); CPA_COMMIT();

    for (int i = 0; i < iters; i++) {
        CPA_WAIT1();
        __syncthreads();
        if (i + 2 < iters) {
            uint32_t stg = sbase + (uint32_t)((i + 2) % 3) * STG_B;
            g2s_stage(Ab + (i + 2) * 32, Bb + (i + 2) * 32, K, stg, tid);
            CPA_COMMIT();
        }
        const uint32_t ab = sbase + (uint32_t)(i % 3) * STG_B + aoff;
        const uint32_t bb = sbase + (uint32_t)(i % 3) * STG_B + boff;

#pragma unroll
        for (int kk = 0; kk < 4; kk++) {
            uint32_t a[2][4], bf[4][4];
#pragma unroll
            for (int im = 0; im < 2; im++)
                LDSM4(a[im], ab + (uint32_t)(im * 16 * GP) * 4 + kk * 32);
#pragma unroll
            for (int nt = 0; nt < 4; nt++)
                LDSM4(bf[nt], bb + (uint32_t)(nt * 16 * GP) * 4 + kk * 32);
#pragma unroll
            for (int im = 0; im < 2; im++)
#pragma unroll
                for (int jn = 0; jn < 8; jn++)
                    MMA_TF32(c[im][jn], a[im],
                             bf[jn >> 1][(jn & 1) * 2],
                             bf[jn >> 1][(jn & 1) * 2 + 1]);
        }
    }

    const int g = lane >> 2, q = lane & 3;
#pragma unroll
    for (int im = 0; im < 2; im++)
#pragma unroll
        for (int jn = 0; jn < 8; jn++) {
            int row = m0 + wm * 32 + im * 16 + g;
            int col = n0 + wn * 64 + jn * 8 + q * 2;
            *(float2*)&C[(size_t)row * N + col]       = make_float2(c[im][jn][0], c[im][jn][1]);
            *(float2*)&C[(size_t)(row + 8) * N + col] = make_float2(c[im][jn][2], c[im][jn][3]);
        }
}

// ---------------- tf32 round-to-nearest copy -------------------------------
__global__ void round_tf32_k(const float4* __restrict__ in, float4* __restrict__ out, int n4) {
    int i = blockIdx.x * blockDim.x + threadIdx.x;
    if (i >= n4) return;
    out[i] = round4(in[i]);
}

// -------- RoPE for Q,K → [b,h,s,d]; Q pre-scaled; both tf32-rounded --------
__global__ void rope_qk(const float* __restrict__ qkv,
                        float* __restrict__ Q, float* __restrict__ K) {
    int idx = blockIdx.x * blockDim.x + threadIdx.x;
    int d  = idx & 127;
    int s  = (idx >> 7) & 2047;
    int bh = idx >> 18;
    int i  = d & 63;
    float theta = (float)s * exp2f(-0.20762050593045998f * (float)i);
    float sn, cs;
    sincosf(theta, &sn, &cs);
    const float* row = qkv + (size_t)((bh >> 4) * 2048 + s) * QKV_N;
    int nq = (bh & 15) * 128;
    float qv = row[nq + d];
    float qp = row[nq + (d ^ 64)];
    float kv = row[2048 + nq + d];
    float kp = row[2048 + nq + (d ^ 64)];
    float qr = (d < 64) ? -qp : qp;
    float kr = (d < 64) ? -kp : kp;
    const float scale = 0.088388347648318447f;   // 1/sqrt(128)
    Q[idx] = to_tf32((qv * cs + qr * sn) * scale);
    K[idx] = to_tf32(kv * cs + kr * sn);
}

// ---------------- V transpose → [b,h,d,s], tf32-rounded --------------------
__global__ void transpose_v(const float* __restrict__ qkv, float* __restrict__ Vt) {
    __shared__ float t[32][33];
    int bh = blockIdx.z;
    int b = bh >> 4, h = bh & 15;
    int s0 = blockIdx.x * 32, d0 = blockIdx.y * 32;
    int tx = threadIdx.x, ty = threadIdx.y;
    const float* src = qkv + ((size_t)(b * SS + s0 + ty)) * QKV_N + 4096 + h * 128 + d0 + tx;
#pragma unroll
    for (int j = 0; j < 32; j += 8)
        t[ty + j][tx] = src[(size_t)j * QKV_N];
    __syncthreads();
    float* dst = Vt + ((size_t)bh * DD + d0 + ty) * SS + s0 + tx;
#pragma unroll
    for (int j = 0; j < 32; j += 8)
        dst[(size_t)j * SS] = to_tf32(t[tx][ty + j]);
}

// ---------------- Flash attention via mma.sync tf32 + cp.async -------------
#define QP 132                               // pitch (floats) for Qs/Ks
#define PP 68                                // pitch for Vs/Ps
#define ATTN2_SMEM ((128 * QP + 64 * QP + 128 * PP + 128 * PP) * 4)

__global__ __launch_bounds__(256, 1)
void attn_mma(const float* __restrict__ Qg_, const float* __restrict__ Kg_,
              const float* __restrict__ Vt_, float* __restrict__ Y) {
    extern __shared__ float sm[];
    float* Qs = sm;                          // [128][QP]  rows=qrow cols=d
    float* Ks = Qs + 128 * QP;               // [64][QP]   rows=kcol cols=d
    float* Vs = Ks + 64 * QP;                // [128][PP]  rows=d    cols=kcol
    float* Ps = Vs + 128 * PP;               // [128][PP]  rows=qrow cols=kcol

    const int tid  = threadIdx.x;
    const int wid  = tid >> 5;
    const int lane = tid & 31;
    const int qb = gridDim.x - 1 - blockIdx.x;   // heavy tiles first
    const int h  = blockIdx.y;
    const int b  = blockIdx.z;
    const int q0 = qb * 128;

    const size_t bh = (size_t)(b * HH + h);
    const float* Qg = Qg_ + bh * SS * DD;    // [s][d] (scaled, tf32)
    const float* Kg = Kg_ + bh * SS * DD;    // [s][d] (tf32)
    const float* Vg = Vt_ + bh * DD * SS;    // [d][s] (tf32)

    const uint32_t qsb = smem_u32(Qs);
    const uint32_t ksb = smem_u32(Ks);
    const uint32_t vsb = smem_u32(Vs);

    // prologue: async Q tile (group 1), K(0) (group 2), V(0) (group 3)
#pragma unroll
    for (int p = 0; p < 16; p++) {           // Q: 128 rows x 32 chunks
        int c = tid + p * 256;
        int row = c >> 5, ch = c & 31;
        CPA16(qsb + (uint32_t)(row * QP + ch * 4) * 4,
              Qg + (size_t)(q0 + row) * DD + ch * 4);
    }
    CPA_COMMIT();
#pragma unroll
    for (int p = 0; p < 8; p++) {            // K: 64 rows x 32 chunks
        int c = tid + p * 256;
        int row = c >> 5, ch = c & 31;
        CPA16(ksb + (uint32_t)(row * QP + ch * 4) * 4,
              Kg + (size_t)row * DD + ch * 4);
    }
    CPA_COMMIT();
#pragma unroll
    for (int p = 0; p < 8; p++) {            // V: 128 rows x 16 chunks
        int c = tid + p * 256;
        int row = c >> 4, ch = c & 15;
        CPA16(vsb + (uint32_t)(row * PP + ch * 4) * 4,
              Vg + (size_t)row * SS + ch * 4);
    }
    CPA_COMMIT();

    const int sub = lane >> 3, r8 = lane & 7;
    const int g = lane >> 2, qq = lane & 3;
    const uint32_t a_q = qsb + (uint32_t)((wid * 16 + (sub & 1) * 8 + r8) * QP + (sub >> 1) * 4) * 4;
    const uint32_t b_k = ksb + (uint32_t)(((sub >> 1) * 8 + r8) * QP + (sub & 1) * 4) * 4;
    const uint32_t a_p = smem_u32(Ps) + (uint32_t)((wid * 16 + (sub & 1) * 8 + r8) * PP + (sub >> 1) * 4) * 4;
    const uint32_t b_v = vsb + (uint32_t)(((sub >> 1) * 8 + r8) * PP + (sub & 1) * 4) * 4;

    float o[16][4];
#pragma unroll
    for (int i = 0; i < 16; i++)
#pragma unroll
        for (int j = 0; j < 4; j++) o[i][j] = 0.f;
    float m0v = -1e30f, m1v = -1e30f, l0 = 0.f, l1 = 0.f;

    const int nkt = 2 * qb + 2;
    for (int kt = 0; kt < nkt; kt++) {
        const int k0 = kt * 64;
        const bool pf = (kt + 1 < nkt);

        // [A] K(kt) (and Q on kt=0) ready
        CPA_WAIT1();
        __syncthreads();

        // S = Q K^T
        float s[8][4];
#pragma unroll
        for (int i = 0; i < 8; i++)
#pragma unroll
            for (int j = 0; j < 4; j++) s[i][j] = 0.f;
#pragma unroll
        for (int kd = 0; kd < 16; kd++) {
            uint32_t a[4];
            LDSM4(a, a_q + kd * 32);
            uint32_t bf[4][4];
#pragma unroll
            for (int nt = 0; nt < 4; nt++)
                LDSM4(bf[nt], b_k + (uint32_t)(nt * 16 * QP) * 4 + kd * 32);
#pragma unroll
            for (int nt = 0; nt < 4; nt++) {
                MMA_TF32(s[nt * 2],     a, bf[nt][0], bf[nt][1]);
                MMA_TF32(s[nt * 2 + 1], a, bf[nt][2], bf[nt][3]);
            }
        }

        // [B] all warps done reading Ks -> prefetch K(kt+1)
        __syncthreads();
        if (pf) {
            int k1 = k0 + 64;
#pragma unroll
            for (int p = 0; p < 8; p++) {
                int c = tid + p * 256;
                int row = c >> 5, ch = c & 31;
                CPA16(ksb + (uint32_t)(row * QP + ch * 4) * 4,
                      Kg + (size_t)(k1 + row) * DD + ch * 4);
            }
            CPA_COMMIT();
        }

        // causal mask (only last two tiles)
        if (kt >= 2 * qb) {
            int row0 = q0 + wid * 16 + g;
#pragma unroll
            for (int j = 0; j < 8; j++) {
                int c = k0 + j * 8 + qq * 2;
                if (c     > row0)     s[j][0] = -1e30f;
                if (c + 1 > row0)     s[j][1] = -1e30f;
                if (c     > row0 + 8) s[j][2] = -1e30f;
                if (c + 1 > row0 + 8) s[j][3] = -1e30f;
            }
        }

        // online softmax
        float tm0 = -1e30f, tm1 = -1e30f;
#pragma unroll
        for (int j = 0; j < 8; j++) {
            tm0 = fmaxf(tm0, fmaxf(s[j][0], s[j][1]));
            tm1 = fmaxf(tm1, fmaxf(s[j][2], s[j][3]));
        }
        tm0 = fmaxf(tm0, __shfl_xor_sync(0xffffffffu, tm0, 1));
        tm0 = fmaxf(tm0, __shfl_xor_sync(0xffffffffu, tm0, 2));
        tm1 = fmaxf(tm1, __shfl_xor_sync(0xffffffffu, tm1, 1));
        tm1 = fmaxf(tm1, __shfl_xor_sync(0xffffffffu, tm1, 2));
        float mn0 = fmaxf(m0v, tm0), mn1 = fmaxf(m1v, tm1);
        float al0 = __expf(m0v - mn0), al1 = __expf(m1v - mn1);
        m0v = mn0; m1v = mn1;
        float rs0 = 0.f, rs1 = 0.f;
#pragma unroll
        for (int j = 0; j < 8; j++) {
            s[j][0] = __expf(s[j][0] - mn0);
            s[j][1] = __expf(s[j][1] - mn0);
            s[j][2] = __expf(s[j][2] - mn1);
            s[j][3] = __expf(s[j][3] - mn1);
            rs0 += s[j][0] + s[j][1];
            rs1 += s[j][2] + s[j][3];
        }
        rs0 += __shfl_xor_sync(0xffffffffu, rs0, 1);
        rs0 += __shfl_xor_sync(0xffffffffu, rs0, 2);
        rs1 += __shfl_xor_sync(0xffffffffu, rs1, 1);
        rs1 += __shfl_xor_sync(0xffffffffu, rs1, 2);
        l0 = l0 * al0 + rs0;
        l1 = l1 * al1 + rs1;
#pragma unroll
        for (int nt = 0; nt < 16; nt++) {
            o[nt][0] *= al0; o[nt][1] *= al0;
            o[nt][2] *= al1; o[nt][3] *= al1;
        }

        // stage P (warp-private rows), tf32-rounded
        {
            int pr0 = (wid * 16 + g) * PP;
#pragma unroll
            for (int j = 0; j < 8; j++) {
                *(float2*)&Ps[pr0 + j * 8 + qq * 2] =
                    make_float2(to_tf32(s[j][0]), to_tf32(s[j][1]));
                *(float2*)&Ps[pr0 + 8 * PP + j * 8 + qq * 2] =
                    make_float2(to_tf32(s[j][2]), to_tf32(s[j][3]));
            }
        }
        __syncwarp();

        // [C] V(kt) ready (leave K(kt+1) in flight if prefetching)
        if (pf) { CPA_WAIT1(); } else { CPA_WAIT0(); }
        __syncthreads();

        // O += P @ V
#pragma unroll
        for (int jk = 0; jk < 8; jk++) {
            uint32_t a[4];
            LDSM4(a, a_p + jk * 32);
#pragma unroll
            for (int nt = 0; nt < 8; nt++) {
                uint32_t bf[4];
                LDSM4(bf, b_v + (uint32_t)(nt * 16 * PP) * 4 + jk * 32);
                MMA_TF32(o[nt * 2],     a, bf[0], bf[1]);
                MMA_TF32(o[nt * 2 + 1], a, bf[2], bf[3]);
            }
        }

        // [D] all warps done reading Vs -> prefetch V(kt+1)
        __syncthreads();
        if (pf) {
            int k1 = k0 + 64;
#pragma unroll
            for (int p = 0; p < 8; p++) {
                int c = tid + p * 256;
                int row = c >> 4, ch = c & 15;
                CPA16(vsb + (uint32_t)(row * PP + ch * 4) * 4,
                      Vg + (size_t)row * SS + k1 + ch * 4);
            }
            CPA_COMMIT();
        }
    }

    // normalize + tf32-round + write Y [b,s,h,d]
    float i0 = 1.f / l0, i1 = 1.f / l1;
    int row0 = q0 + wid * 16 + g;
    size_t base0 = ((size_t)b * SS + row0) * EE + h * 128;
    size_t base1 = base0 + (size_t)8 * EE;
#pragma unroll
    for (int nt = 0; nt < 16; nt++) {
        int col = nt * 8 + qq * 2;
        *(float2*)&Y[base0 + col] =
            make_float2(to_tf32(o[nt][0] * i0), to_tf32(o[nt][1] * i0));
        *(float2*)&Y[base1 + col] =
            make_float2(to_tf32(o[nt][2] * i1), to_tf32(o[nt][3] * i1));
    }
}

// ---------------- launch -----------------------------------------------------
extern "C" void kernel_launch(void* const* d_in, const int* in_sizes, int n_in,
                              void* d_out, int out_size) {
    const float* x     = (const float*)d_in[0];
    const float* w_qkv = (const float*)d_in[1];
    const float* w_out = (const float*)d_in[2];
    float* out = (float*)d_out;

    float *p_x, *p_wqkv, *p_wout, *p_qkv, *p_Q, *p_K, *p_Vt, *p_y;
    cudaGetSymbolAddress((void**)&p_x,    g_x);
    cudaGetSymbolAddress((void**)&p_wqkv, g_wqkv);
    cudaGetSymbolAddress((void**)&p_wout, g_wout);
    cudaGetSymbolAddress((void**)&p_qkv,  g_qkv);
    cudaGetSymbolAddress((void**)&p_Q,    g_Q);
    cudaGetSymbolAddress((void**)&p_K,    g_K);
    cudaGetSymbolAddress((void**)&p_Vt,   g_Vt);
    cudaGetSymbolAddress((void**)&p_y,    g_y);

    cudaFuncSetAttribute(gemm_mma, cudaFuncAttributeMaxDynamicSharedMemorySize, GEMM_SMEM);
    cudaFuncSetAttribute(attn_mma, cudaFuncAttributeMaxDynamicSharedMemorySize, ATTN2_SMEM);

    // 0) round GEMM operands to tf32 (RNA)
    round_tf32_k<<<(MROWS * EE / 4 + 255) / 256, 256>>>((const float4*)x, (float4*)p_x, MROWS * EE / 4);
    round_tf32_k<<<(QKV_N * EE / 4 + 255) / 256, 256>>>((const float4*)w_qkv, (float4*)p_wqkv, QKV_N * EE / 4);
    round_tf32_k<<<(EE * EE / 4 + 255) / 256, 256>>>((const float4*)w_out, (float4*)p_wout, EE * EE / 4);

    // 1) qkv = x @ w_qkv^T
    gemm_mma<<<dim3(QKV_N / 128, MROWS / 128), 256, GEMM_SMEM>>>(p_x, p_wqkv, p_qkv, QKV_N, EE);
    // 2) RoPE → Q,K [b,h,s,d] (tf32, Q scaled); V transpose → [b,h,d,s] (tf32)
    rope_qk<<<(BB * HH * SS * DD) / 256, 256>>>(p_qkv, p_Q, p_K);
    transpose_v<<<dim3(SS / 32, DD / 32, BB * HH), dim3(32, 8)>>>(p_qkv, p_Vt);
    // 3) flash attention (mma.sync tf32, cp.async pipelined)
    attn_mma<<<dim3(SS / 128, HH, BB), 256, ATTN2_SMEM>>>(p_Q, p_K, p_Vt, p_y);
    // 4) out = y @ w_out^T
    gemm_mma<<<dim3(EE / 128, MROWS / 128), 256, GEMM_SMEM>>>(p_y, p_wout, out, EE, EE);
}

// round 10
// speedup vs baseline: 1.3190x; 1.0257x over previous
#include <cuda_runtime.h>
#include <cuda_bf16.h>
#include <cstdint>
#include <math.h>

// Problem constants
#define BB 2
#define SS 2048
#define EE 2048
#define HH 16
#define DD 128
#define MROWS (BB * SS)          // 4096
#define QKV_N (3 * EE)           // 6144

// ---------------- scratch (device globals: allocation-free) ----------------
__device__ float g_x   [(size_t)MROWS * EE];            // tf32-rounded x
__device__ float g_wqkv[(size_t)QKV_N * EE];            // tf32-rounded w_qkv
__device__ float g_wout[(size_t)EE * EE];               // tf32-rounded w_out
__device__ float g_Q   [(size_t)BB * HH * SS * DD];     // [b,h,s,d] roped, scaled, tf32
__device__ float g_K   [(size_t)BB * HH * SS * DD];     // [b,h,s,d] roped, tf32
__device__ float g_Vt  [(size_t)BB * HH * DD * SS];     // [b,h,d,s] tf32
__device__ float g_y   [(size_t)MROWS * EE];            // [b,s,h,d], tf32-rounded
__device__ float2 g_rope[(size_t)SS * 64];              // (cos,sin) per (s, i)

// ======================= helpers ===========================================
__device__ __forceinline__ uint32_t smem_u32(const void* p) {
    uint32_t a;
    asm("{ .reg .u64 t; cvta.to.shared.u64 t, %1; cvt.u32.u64 %0, t; }"
        : "=r"(a) : "l"(p));
    return a;
}

__device__ __forceinline__ float to_tf32(float x) {
    uint32_t u;
    asm("cvt.rna.tf32.f32 %0, %1;" : "=r"(u) : "f"(x));
    return __uint_as_float(u);
}

__device__ __forceinline__ float4 round4(float4 v) {
    v.x = to_tf32(v.x); v.y = to_tf32(v.y);
    v.z = to_tf32(v.z); v.w = to_tf32(v.w);
    return v;
}

#define CPA16(dst, src) \
    asm volatile("cp.async.cg.shared.global [%0], [%1], 16;" :: "r"(dst), "l"(src))
#define CPA_COMMIT()  asm volatile("cp.async.commit_group;" ::: "memory")
#define CPA_WAIT1()   asm volatile("cp.async.wait_group 1;" ::: "memory")
#define CPA_WAIT0()   asm volatile("cp.async.wait_group 0;" ::: "memory")

#define LDSM4(r, addr)                                                        \
    asm volatile("ldmatrix.sync.aligned.m8n8.x4.shared.b16 {%0,%1,%2,%3}, [%4];" \
        : "=r"((r)[0]), "=r"((r)[1]), "=r"((r)[2]), "=r"((r)[3]) : "r"(addr))

#define MMA_TF32(c, a, b0, b1)                                                \
    asm volatile("mma.sync.aligned.m16n8k8.row.col.f32.tf32.tf32.f32 "        \
        "{%0,%1,%2,%3}, {%4,%5,%6,%7}, {%8,%9}, {%0,%1,%2,%3};"               \
        : "+f"((c)[0]), "+f"((c)[1]), "+f"((c)[2]), "+f"((c)[3])              \
        : "r"((a)[0]), "r"((a)[1]), "r"((a)[2]), "r"((a)[3]), "r"(b0), "r"(b1))

// ============ mma.sync tf32 GEMM: C[M,N] = A[M,K] @ B[N,K]^T ===============
// CTA 128x128, 256 thr / 8 warps (4m x 2n), warptile 32x64, 3-stage cp.async
// 2 CTAs per SM. FUSE=1: QKV epilogue (RoPE q/k, transpose v), FUSE=0: plain C.
#define GP 36                                // SMEM pitch (floats), %32==4
#define BOFF (128 * GP * 4)                  // B offset within stage (bytes)
#define STG_B ((128 + 128) * GP * 4)         // 36864 bytes
#define GEMM_SMEM (3 * STG_B)                // 110592 bytes

__device__ __forceinline__ void g2s_stage(const float* A, const float* B, int K,
                                          uint32_t stg, int tid) {
#pragma unroll
    for (int j = 0; j < 4; j++) {            // A: 128 rows x 8 chunks
        int cid = tid + j * 256;
        int row = cid >> 3, chk = cid & 7;
        CPA16(stg + (uint32_t)(row * GP + chk * 4) * 4,
              A + (size_t)row * K + chk * 4);
    }
#pragma unroll
    for (int j = 0; j < 4; j++) {            // B: 128 rows x 8 chunks
        int cid = tid + j * 256;
        int row = cid >> 3, chk = cid & 7;
        CPA16(stg + BOFF + (uint32_t)(row * GP + chk * 4) * 4,
              B + (size_t)row * K + chk * 4);
    }
}

template<int FUSE>
__global__ __launch_bounds__(256, 2)
void gemm_k(const float* __restrict__ A, const float* __restrict__ B,
            float* __restrict__ C,
            float* __restrict__ Qo, float* __restrict__ Ko, float* __restrict__ Vo,
            const float2* __restrict__ rt, int N, int K) {
    extern __shared__ char smem[];
    const uint32_t sbase = smem_u32(smem);
    const int tid  = threadIdx.x;
    const int wid  = tid >> 5;
    const int lane = tid & 31;
    const int wm   = wid >> 1;               // 0..3 (32 rows)
    const int wn   = wid & 1;                // 0..1 (64 cols)
    const int m0 = blockIdx.y * 128;
    const int n0 = blockIdx.x * 128;
    const int iters = K >> 5;

    const float* Ab = A + (size_t)m0 * K;
    const float* Bb = B + (size_t)n0 * K;

    float c[2][8][4];
#pragma unroll
    for (int i = 0; i < 2; i++)
#pragma unroll
        for (int j = 0; j < 8; j++)
#pragma unroll
            for (int q = 0; q < 4; q++) c[i][j][q] = 0.f;

    const int sub = lane >> 3;
    const int r8  = lane & 7;
    const uint32_t aoff = (uint32_t)((wm * 32 + (sub & 1) * 8 + r8) * GP + (sub >> 1) * 4) * 4;
    const uint32_t boff = BOFF + (uint32_t)((wn * 64 + (sub >> 1) * 8 + r8) * GP + (sub & 1) * 4) * 4;

    g2s_stage(Ab, Bb, K, sbase, tid);                   CPA_COMMIT();
    g2s_stage(Ab + 32, Bb + 32, K, sbase + STG_B, tid); CPA_COMMIT();

    for (int i = 0; i < iters; i++) {
        CPA_WAIT1();
        __syncthreads();
        if (i + 2 < iters) {
            uint32_t stg = sbase + (uint32_t)((i + 2) % 3) * STG_B;
            g2s_stage(Ab + (i + 2) * 32, Bb + (i + 2) * 32, K, stg, tid);
            CPA_COMMIT();
        }
        const uint32_t ab = sbase + (uint32_t)(i % 3) * STG_B + aoff;
        const uint32_t bb = sbase + (uint32_t)(i % 3) * STG_B + boff;

#pragma unroll
        for (int kk = 0; kk < 4; kk++) {
            uint32_t a[2][4], bf[4][4];
#pragma unroll
            for (int im = 0; im < 2; im++)
                LDSM4(a[im], ab + (uint32_t)(im * 16 * GP) * 4 + kk * 32);
#pragma unroll
            for (int nt = 0; nt < 4; nt++)
                LDSM4(bf[nt], bb + (uint32_t)(nt * 16 * GP) * 4 + kk * 32);
#pragma unroll
            for (int im = 0; im < 2; im++)
#pragma unroll
                for (int jn = 0; jn < 8; jn++)
                    MMA_TF32(c[im][jn], a[im],
                             bf[jn >> 1][(jn & 1) * 2],
                             bf[jn >> 1][(jn & 1) * 2 + 1]);
        }
    }

    const int g = lane >> 2, q = lane & 3;

    if (FUSE == 0) {
#pragma unroll
        for (int im = 0; im < 2; im++)
#pragma unroll
            for (int jn = 0; jn < 8; jn++) {
                int row = m0 + wm * 32 + im * 16 + g;
                int col = n0 + wn * 64 + jn * 8 + q * 2;
                *(float2*)&C[(size_t)row * N + col]       = make_float2(c[im][jn][0], c[im][jn][1]);
                *(float2*)&C[(size_t)(row + 8) * N + col] = make_float2(c[im][jn][2], c[im][jn][3]);
            }
    } else {
        // ---- fused QKV epilogue: stage tile, apply RoPE / transpose ----
        CPA_WAIT0();
        __syncthreads();                      // all warps done with stage SMEM
        float* Cs = (float*)smem;             // [128][132]
#pragma unroll
        for (int im = 0; im < 2; im++)
#pragma unroll
            for (int jn = 0; jn < 8; jn++) {
                int row = wm * 32 + im * 16 + g;
                int col = wn * 64 + jn * 8 + q * 2;
                *(float2*)&Cs[row * 132 + col]       = make_float2(c[im][jn][0], c[im][jn][1]);
                *(float2*)&Cs[(row + 8) * 132 + col] = make_float2(c[im][jn][2], c[im][jn][3]);
            }
        __syncthreads();

        const int hb   = n0 >> 7;             // 0..47
        const int type = hb >> 4;             // 0=q,1=k,2=v
        const int h    = hb & 15;
        const int b    = m0 >> 11;
        const int s0   = m0 & 2047;
        const size_t bh = (size_t)(b * HH + h);

        if (type < 2) {
            float* Out = (type == 0) ? Qo : Ko;
            const float scl = (type == 0) ? 0.088388347648318447f : 1.0f;
#pragma unroll
            for (int p = 0; p < 16; p++) {
                int idx = tid + p * 256;
                int row = idx >> 5, col = (idx & 31) * 4;
                int s = s0 + row;
                float4 v = *(float4*)&Cs[row * 132 + col];
                float4 w = *(float4*)&Cs[row * 132 + (col ^ 64)];
                float ov[4];
#pragma unroll
                for (int j = 0; j < 4; j++) {
                    int d = col + j;
                    float2 t = rt[s * 64 + (d & 63)];
                    float val  = (&v.x)[j];
                    float part = (&w.x)[j];
                    float r = (d < 64) ? -part : part;
                    ov[j] = to_tf32((val * t.x + r * t.y) * scl);
                }
                *(float4*)&Out[(bh * SS + s) * DD + col] =
                    make_float4(ov[0], ov[1], ov[2], ov[3]);
            }
        } else {
#pragma unroll
            for (int p = 0; p < 16; p++) {
                int idx = tid + p * 256;
                int d = idx >> 5, ch = idx & 31;
                float* vrow = Vo + (bh * DD + d) * SS + s0;
#pragma unroll
                for (int j = 0; j < 4; j++) {
                    int s = ch + j * 32;
                    vrow[s] = to_tf32(Cs[s * 132 + d]);
                }
            }
        }
    }
}

// ---------------- tf32 round-to-nearest copy -------------------------------
__global__ void round_tf32_k(const float4* __restrict__ in, float4* __restrict__ out, int n4) {
    int i = blockIdx.x * blockDim.x + threadIdx.x;
    if (i >= n4) return;
    out[i] = round4(in[i]);
}

// ---------------- RoPE cos/sin table ---------------------------------------
__global__ void rope_table(float2* __restrict__ rt) {
    int idx = blockIdx.x * blockDim.x + threadIdx.x;   // SS*64
    int i = idx & 63, s = idx >> 6;
    float theta = (float)s * exp2f(-0.20762050593045998f * (float)i);
    float sn, cs;
    sincosf(theta, &sn, &cs);
    rt[idx] = make_float2(cs, sn);
}

// ---------------- Flash attention via mma.sync tf32 + cp.async -------------
#define QP 132                               // pitch (floats) for Qs/Ks
#define PP 68                                // pitch for Vs/Ps
#define ATTN2_SMEM ((128 * QP + 64 * QP + 128 * PP + 128 * PP) * 4)

__global__ __launch_bounds__(256, 1)
void attn_mma(const float* __restrict__ Qg_, const float* __restrict__ Kg_,
              const float* __restrict__ Vt_, float* __restrict__ Y) {
    extern __shared__ float sm[];
    float* Qs = sm;                          // [128][QP]  rows=qrow cols=d
    float* Ks = Qs + 128 * QP;               // [64][QP]   rows=kcol cols=d
    float* Vs = Ks + 64 * QP;                // [128][PP]  rows=d    cols=kcol
    float* Ps = Vs + 128 * PP;               // [128][PP]  rows=qrow cols=kcol

    const int tid  = threadIdx.x;
    const int wid  = tid >> 5;
    const int lane = tid & 31;
    const int qb = gridDim.x - 1 - blockIdx.x;   // heavy tiles first
    const int h  = blockIdx.y;
    const int b  = blockIdx.z;
    const int q0 = qb * 128;

    const size_t bh = (size_t)(b * HH + h);
    const float* Qg = Qg_ + bh * SS * DD;    // [s][d] (scaled, tf32)
    const float* Kg = Kg_ + bh * SS * DD;    // [s][d] (tf32)
    const float* Vg = Vt_ + bh * DD * SS;    // [d][s] (tf32)

    const uint32_t qsb = smem_u32(Qs);
    const uint32_t ksb = smem_u32(Ks);
    const uint32_t vsb = smem_u32(Vs);

    // prologue: async Q tile (group 1), K(0) (group 2), V(0) (group 3)
#pragma unroll
    for (int p = 0; p < 16; p++) {           // Q: 128 rows x 32 chunks
        int c = tid + p * 256;
        int row = c >> 5, ch = c & 31;
        CPA16(qsb + (uint32_t)(row * QP + ch * 4) * 4,
              Qg + (size_t)(q0 + row) * DD + ch * 4);
    }
    CPA_COMMIT();
#pragma unroll
    for (int p = 0; p < 8; p++) {            // K: 64 rows x 32 chunks
        int c = tid + p * 256;
        int row = c >> 5, ch = c & 31;
        CPA16(ksb + (uint32_t)(row * QP + ch * 4) * 4,
              Kg + (size_t)row * DD + ch * 4);
    }
    CPA_COMMIT();
#pragma unroll
    for (int p = 0; p < 8; p++) {            // V: 128 rows x 16 chunks
        int c = tid + p * 256;
        int row = c >> 4, ch = c & 15;
        CPA16(vsb + (uint32_t)(row * PP + ch * 4) * 4,
              Vg + (size_t)row * SS + ch * 4);
    }
    CPA_COMMIT();

    const int sub = lane >> 3, r8 = lane & 7;
    const int g = lane >> 2, qq = lane & 3;
    const uint32_t a_q = qsb + (uint32_t)((wid * 16 + (sub & 1) * 8 + r8) * QP + (sub >> 1) * 4) * 4;
    const uint32_t b_k = ksb + (uint32_t)(((sub >> 1) * 8 + r8) * QP + (sub & 1) * 4) * 4;
    const uint32_t a_p = smem_u32(Ps) + (uint32_t)((wid * 16 + (sub & 1) * 8 + r8) * PP + (sub >> 1) * 4) * 4;
    const uint32_t b_v = vsb + (uint32_t)(((sub >> 1) * 8 + r8) * PP + (sub & 1) * 4) * 4;

    float o[16][4];
#pragma unroll
    for (int i = 0; i < 16; i++)
#pragma unroll
        for (int j = 0; j < 4; j++) o[i][j] = 0.f;
    float m0v = -1e30f, m1v = -1e30f, l0 = 0.f, l1 = 0.f;

    const int nkt = 2 * qb + 2;
    for (int kt = 0; kt < nkt; kt++) {
        const int k0 = kt * 64;
        const bool pf = (kt + 1 < nkt);

        // [A] K(kt) (and Q on kt=0) ready
        CPA_WAIT1();
        __syncthreads();

        // S = Q K^T
        float s[8][4];
#pragma unroll
        for (int i = 0; i < 8; i++)
#pragma unroll
            for (int j = 0; j < 4; j++) s[i][j] = 0.f;
#pragma unroll
        for (int kd = 0; kd < 16; kd++) {
            uint32_t a[4];
            LDSM4(a, a_q + kd * 32);
            uint32_t bf[4][4];
#pragma unroll
            for (int nt = 0; nt < 4; nt++)
                LDSM4(bf[nt], b_k + (uint32_t)(nt * 16 * QP) * 4 + kd * 32);
#pragma unroll
            for (int nt = 0; nt < 4; nt++) {
                MMA_TF32(s[nt * 2],     a, bf[nt][0], bf[nt][1]);
                MMA_TF32(s[nt * 2 + 1], a, bf[nt][2], bf[nt][3]);
            }
        }

        // [B] all warps done reading Ks -> prefetch K(kt+1)
        __syncthreads();
        if (pf) {
            int k1 = k0 + 64;
#pragma unroll
            for (int p = 0; p < 8; p++) {
                int c = tid + p * 256;
                int row = c >> 5, ch = c & 31;
                CPA16(ksb + (uint32_t)(row * QP + ch * 4) * 4,
                      Kg + (size_t)(k1 + row) * DD + ch * 4);
            }
            CPA_COMMIT();
        }

        // causal mask (only last two tiles)
        if (kt >= 2 * qb) {
            int row0 = q0 + wid * 16 + g;
#pragma unroll
            for (int j = 0; j < 8; j++) {
                int c = k0 + j * 8 + qq * 2;
                if (c     > row0)     s[j][0] = -1e30f;
                if (c + 1 > row0)     s[j][1] = -1e30f;
                if (c     > row0 + 8) s[j][2] = -1e30f;
                if (c + 1 > row0 + 8) s[j][3] = -1e30f;
            }
        }

        // online softmax
        float tm0 = -1e30f, tm1 = -1e30f;
#pragma unroll
        for (int j = 0; j < 8; j++) {
            tm0 = fmaxf(tm0, fmaxf(s[j][0], s[j][1]));
            tm1 = fmaxf(tm1, fmaxf(s[j][2], s[j][3]));
        }
        tm0 = fmaxf(tm0, __shfl_xor_sync(0xffffffffu, tm0, 1));
        tm0 = fmaxf(tm0, __shfl_xor_sync(0xffffffffu, tm0, 2));
        tm1 = fmaxf(tm1, __shfl_xor_sync(0xffffffffu, tm1, 1));
        tm1 = fmaxf(tm1, __shfl_xor_sync(0xffffffffu, tm1, 2));
        float mn0 = fmaxf(m0v, tm0), mn1 = fmaxf(m1v, tm1);
        float al0 = __expf(m0v - mn0), al1 = __expf(m1v - mn1);
        m0v = mn0; m1v = mn1;
        float rs0 = 0.f, rs1 = 0.f;
#pragma unroll
        for (int j = 0; j < 8; j++) {
            s[j][0] = __expf(s[j][0] - mn0);
            s[j][1] = __expf(s[j][1] - mn0);
            s[j][2] = __expf(s[j][2] - mn1);
            s[j][3] = __expf(s[j][3] - mn1);
            rs0 += s[j][0] + s[j][1];
            rs1 += s[j][2] + s[j][3];
        }
        rs0 += __shfl_xor_sync(0xffffffffu, rs0, 1);
        rs0 += __shfl_xor_sync(0xffffffffu, rs0, 2);
        rs1 += __shfl_xor_sync(0xffffffffu, rs1, 1);
        rs1 += __shfl_xor_sync(0xffffffffu, rs1, 2);
        l0 = l0 * al0 + rs0;
        l1 = l1 * al1 + rs1;
#pragma unroll
        for (int nt = 0; nt < 16; nt++) {
            o[nt][0] *= al0; o[nt][1] *= al0;
            o[nt][2] *= al1; o[nt][3] *= al1;
        }

        // stage P (warp-private rows), tf32-rounded
        {
            int pr0 = (wid * 16 + g) * PP;
#pragma unroll
            for (int j = 0; j < 8; j++) {
                *(float2*)&Ps[pr0 + j * 8 + qq * 2] =
                    make_float2(to_tf32(s[j][0]), to_tf32(s[j][1]));
                *(float2*)&Ps[pr0 + 8 * PP + j * 8 + qq * 2] =
                    make_float2(to_tf32(s[j][2]), to_tf32(s[j][3]));
            }
        }
        __syncwarp();

        // [C] V(kt) ready (leave K(kt+1) in flight if prefetching)
        if (pf) { CPA_WAIT1(); } else { CPA_WAIT0(); }
        __syncthreads();

        // O += P @ V
#pragma unroll
        for (int jk = 0; jk < 8; jk++) {
            uint32_t a[4];
            LDSM4(a, a_p + jk * 32);
#pragma unroll
            for (int nt = 0; nt < 8; nt++) {
                uint32_t bf[4];
                LDSM4(bf, b_v + (uint32_t)(nt * 16 * PP) * 4 + jk * 32);
                MMA_TF32(o[nt * 2],     a, bf[0], bf[1]);
                MMA_TF32(o[nt * 2 + 1], a, bf[2], bf[3]);
            }
        }

        // [D] all warps done reading Vs -> prefetch V(kt+1)
        __syncthreads();
        if (pf) {
            int k1 = k0 + 64;
#pragma unroll
            for (int p = 0; p < 8; p++) {
                int c = tid + p * 256;
                int row = c >> 4, ch = c & 15;
                CPA16(vsb + (uint32_t)(row * PP + ch * 4) * 4,
                      Vg + (size_t)row * SS + k1 + ch * 4);
            }
            CPA_COMMIT();
        }
    }

    // normalize + tf32-round + write Y [b,s,h,d]
    float i0 = 1.f / l0, i1 = 1.f / l1;
    int row0 = q0 + wid * 16 + g;
    size_t base0 = ((size_t)b * SS + row0) * EE + h * 128;
    size_t base1 = base0 + (size_t)8 * EE;
#pragma unroll
    for (int nt = 0; nt < 16; nt++) {
        int col = nt * 8 + qq * 2;
        *(float2*)&Y[base0 + col] =
            make_float2(to_tf32(o[nt][0] * i0), to_tf32(o[nt][1] * i0));
        *(float2*)&Y[base1 + col] =
            make_float2(to_tf32(o[nt][2] * i1), to_tf32(o[nt][3] * i1));
    }
}

// ---------------- launch -----------------------------------------------------
extern "C" void kernel_launch(void* const* d_in, const int* in_sizes, int n_in,
                              void* d_out, int out_size) {
    const float* x     = (const float*)d_in[0];
    const float* w_qkv = (const float*)d_in[1];
    const float* w_out = (const float*)d_in[2];
    float* out = (float*)d_out;

    float *p_x, *p_wqkv, *p_wout, *p_Q, *p_K, *p_Vt, *p_y;
    float2* p_rope;
    cudaGetSymbolAddress((void**)&p_x,    g_x);
    cudaGetSymbolAddress((void**)&p_wqkv, g_wqkv);
    cudaGetSymbolAddress((void**)&p_wout, g_wout);
    cudaGetSymbolAddress((void**)&p_Q,    g_Q);
    cudaGetSymbolAddress((void**)&p_K,    g_K);
    cudaGetSymbolAddress((void**)&p_Vt,   g_Vt);
    cudaGetSymbolAddress((void**)&p_y,    g_y);
    cudaGetSymbolAddress((void**)&p_rope, g_rope);

    cudaFuncSetAttribute(gemm_k<0>, cudaFuncAttributeMaxDynamicSharedMemorySize, GEMM_SMEM);
    cudaFuncSetAttribute(gemm_k<1>, cudaFuncAttributeMaxDynamicSharedMemorySize, GEMM_SMEM);
    cudaFuncSetAttribute(attn_mma, cudaFuncAttributeMaxDynamicSharedMemorySize, ATTN2_SMEM);

    // 0) round GEMM operands to tf32 (RNA); build rope table
    round_tf32_k<<<(MROWS * EE / 4 + 255) / 256, 256>>>((const float4*)x, (float4*)p_x, MROWS * EE / 4);
    round_tf32_k<<<(QKV_N * EE / 4 + 255) / 256, 256>>>((const float4*)w_qkv, (float4*)p_wqkv, QKV_N * EE / 4);
    round_tf32_k<<<(EE * EE / 4 + 255) / 256, 256>>>((const float4*)w_out, (float4*)p_wout, EE * EE / 4);
    rope_table<<<(SS * 64) / 256, 256>>>(p_rope);

    // 1) fused: qkv GEMM + RoPE(q,k) + V transpose  → g_Q, g_K, g_Vt
    gemm_k<1><<<dim3(QKV_N / 128, MROWS / 128), 256, GEMM_SMEM>>>(
        p_x, p_wqkv, nullptr, p_Q, p_K, p_Vt, p_rope, QKV_N, EE);
    // 2) flash attention (mma.sync tf32, cp.async pipelined)
    attn_mma<<<dim3(SS / 128, HH, BB), 256, ATTN2_SMEM>>>(p_Q, p_K, p_Vt, p_y);
    // 3) out = y @ w_out^T
    gemm_k<0><<<dim3(EE / 128, MROWS / 128), 256, GEMM_SMEM>>>(
        p_y, p_wout, out, nullptr, nullptr, nullptr, nullptr, EE, EE);
}

// round 11
// speedup vs baseline: 1.3198x; 1.0006x over previous
#include <cuda_runtime.h>
#include <cuda_bf16.h>
#include <cstdint>
#include <math.h>

// Problem constants
#define BB 2
#define SS 2048
#define EE 2048
#define HH 16
#define DD 128
#define MROWS (BB * SS)          // 4096
#define QKV_N (3 * EE)           // 6144

// ---------------- scratch (device globals: allocation-free) ----------------
__device__ float g_x   [(size_t)MROWS * EE];            // tf32-rounded x
__device__ float g_wqkv[(size_t)QKV_N * EE];            // tf32-rounded w_qkv
__device__ float g_wout[(size_t)EE * EE];               // tf32-rounded w_out
__device__ float g_Q   [(size_t)BB * HH * SS * DD];     // [b,h,s,d] roped, scaled, tf32
__device__ float g_K   [(size_t)BB * HH * SS * DD];     // [b,h,s,d] roped, tf32
__device__ float g_Vt  [(size_t)BB * HH * DD * SS];     // [b,h,d,s] tf32
__device__ float g_y   [(size_t)MROWS * EE];            // [b,s,h,d], tf32-rounded
__device__ float2 g_rope[(size_t)SS * 64];              // (cos,sin) per (s, i)

// ======================= helpers ===========================================
__device__ __forceinline__ uint32_t smem_u32(const void* p) {
    uint32_t a;
    asm("{ .reg .u64 t; cvta.to.shared.u64 t, %1; cvt.u32.u64 %0, t; }"
        : "=r"(a) : "l"(p));
    return a;
}

__device__ __forceinline__ float to_tf32(float x) {
    uint32_t u;
    asm("cvt.rna.tf32.f32 %0, %1;" : "=r"(u) : "f"(x));
    return __uint_as_float(u);
}

__device__ __forceinline__ float4 round4(float4 v) {
    v.x = to_tf32(v.x); v.y = to_tf32(v.y);
    v.z = to_tf32(v.z); v.w = to_tf32(v.w);
    return v;
}

#define CPA16(dst, src) \
    asm volatile("cp.async.cg.shared.global [%0], [%1], 16;" :: "r"(dst), "l"(src))
#define CPA_COMMIT()  asm volatile("cp.async.commit_group;" ::: "memory")
#define CPA_WAIT1()   asm volatile("cp.async.wait_group 1;" ::: "memory")
#define CPA_WAIT0()   asm volatile("cp.async.wait_group 0;" ::: "memory")

#define LDSM4(r, addr)                                                        \
    asm volatile("ldmatrix.sync.aligned.m8n8.x4.shared.b16 {%0,%1,%2,%3}, [%4];" \
        : "=r"((r)[0]), "=r"((r)[1]), "=r"((r)[2]), "=r"((r)[3]) : "r"(addr))

#define MMA_TF32(c, a, b0, b1)                                                \
    asm volatile("mma.sync.aligned.m16n8k8.row.col.f32.tf32.tf32.f32 "        \
        "{%0,%1,%2,%3}, {%4,%5,%6,%7}, {%8,%9}, {%0,%1,%2,%3};"               \
        : "+f"((c)[0]), "+f"((c)[1]), "+f"((c)[2]), "+f"((c)[3])              \
        : "r"((a)[0]), "r"((a)[1]), "r"((a)[2]), "r"((a)[3]), "r"(b0), "r"(b1))

// ============ mma.sync tf32 GEMM: C[M,N] = A[M,K] @ B[N,K]^T ===============
// CTA 128x128, 256 thr / 8 warps (4m x 2n), warptile 32x64, 3-stage cp.async
// 2 CTAs per SM. FUSE=1: QKV epilogue (RoPE q/k, transpose v), FUSE=0: plain C.
#define GP 36                                // SMEM pitch (floats), %32==4
#define BOFF (128 * GP * 4)                  // B offset within stage (bytes)
#define STG_B ((128 + 128) * GP * 4)         // 36864 bytes
#define GEMM_SMEM (3 * STG_B)                // 110592 bytes

__device__ __forceinline__ void g2s_stage(const float* A, const float* B, int K,
                                          uint32_t stg, int tid) {
#pragma unroll
    for (int j = 0; j < 4; j++) {            // A: 128 rows x 8 chunks
        int cid = tid + j * 256;
        int row = cid >> 3, chk = cid & 7;
        CPA16(stg + (uint32_t)(row * GP + chk * 4) * 4,
              A + (size_t)row * K + chk * 4);
    }
#pragma unroll
    for (int j = 0; j < 4; j++) {            // B: 128 rows x 8 chunks
        int cid = tid + j * 256;
        int row = cid >> 3, chk = cid & 7;
        CPA16(stg + BOFF + (uint32_t)(row * GP + chk * 4) * 4,
              B + (size_t)row * K + chk * 4);
    }
}

template<int FUSE>
__global__ __launch_bounds__(256, 2)
void gemm_k(const float* __restrict__ A, const float* __restrict__ B,
            float* __restrict__ C,
            float* __restrict__ Qo, float* __restrict__ Ko, float* __restrict__ Vo,
            const float2* __restrict__ rt, int N, int K) {
    extern __shared__ char smem[];
    const uint32_t sbase = smem_u32(smem);
    const int tid  = threadIdx.x;
    const int wid  = tid >> 5;
    const int lane = tid & 31;
    const int wm   = wid >> 1;               // 0..3 (32 rows)
    const int wn   = wid & 1;                // 0..1 (64 cols)
    const int m0 = blockIdx.y * 128;
    const int n0 = blockIdx.x * 128;
    const int iters = K >> 5;

    const float* Ab = A + (size_t)m0 * K;
    const float* Bb = B + (size_t)n0 * K;

    float c[2][8][4];
#pragma unroll
    for (int i = 0; i < 2; i++)
#pragma unroll
        for (int j = 0; j < 8; j++)
#pragma unroll
            for (int q = 0; q < 4; q++) c[i][j][q] = 0.f;

    const int sub = lane >> 3;
    const int r8  = lane & 7;
    const uint32_t aoff = (uint32_t)((wm * 32 + (sub & 1) * 8 + r8) * GP + (sub >> 1) * 4) * 4;
    const uint32_t boff = BOFF + (uint32_t)((wn * 64 + (sub >> 1) * 8 + r8) * GP + (sub & 1) * 4) * 4;

    g2s_stage(Ab, Bb, K, sbase, tid);                   CPA_COMMIT();
    g2s_stage(Ab + 32, Bb + 32, K, sbase + STG_B, tid); CPA_COMMIT();

    for (int i = 0; i < iters; i++) {
        CPA_WAIT1();
        __syncthreads();
        if (i + 2 < iters) {
            uint32_t stg = sbase + (uint32_t)((i + 2) % 3) * STG_B;
            g2s_stage(Ab + (i + 2) * 32, Bb + (i + 2) * 32, K, stg, tid);
            CPA_COMMIT();
        }
        const uint32_t ab = sbase + (uint32_t)(i % 3) * STG_B + aoff;
        const uint32_t bb = sbase + (uint32_t)(i % 3) * STG_B + boff;

#pragma unroll
        for (int kk = 0; kk < 4; kk++) {
            uint32_t a[2][4], bf[4][4];
#pragma unroll
            for (int im = 0; im < 2; im++)
                LDSM4(a[im], ab + (uint32_t)(im * 16 * GP) * 4 + kk * 32);
#pragma unroll
            for (int nt = 0; nt < 4; nt++)
                LDSM4(bf[nt], bb + (uint32_t)(nt * 16 * GP) * 4 + kk * 32);
#pragma unroll
            for (int im = 0; im < 2; im++)
#pragma unroll
                for (int jn = 0; jn < 8; jn++)
                    MMA_TF32(c[im][jn], a[im],
                             bf[jn >> 1][(jn & 1) * 2],
                             bf[jn >> 1][(jn & 1) * 2 + 1]);
        }
    }

    const int g = lane >> 2, q = lane & 3;

    if (FUSE == 0) {
#pragma unroll
        for (int im = 0; im < 2; im++)
#pragma unroll
            for (int jn = 0; jn < 8; jn++) {
                int row = m0 + wm * 32 + im * 16 + g;
                int col = n0 + wn * 64 + jn * 8 + q * 2;
                *(float2*)&C[(size_t)row * N + col]       = make_float2(c[im][jn][0], c[im][jn][1]);
                *(float2*)&C[(size_t)(row + 8) * N + col] = make_float2(c[im][jn][2], c[im][jn][3]);
            }
    } else {
        // ---- fused QKV epilogue: stage tile, apply RoPE / transpose ----
        CPA_WAIT0();
        __syncthreads();                      // all warps done with stage SMEM
        float* Cs = (float*)smem;             // [128][132]
#pragma unroll
        for (int im = 0; im < 2; im++)
#pragma unroll
            for (int jn = 0; jn < 8; jn++) {
                int row = wm * 32 + im * 16 + g;
                int col = wn * 64 + jn * 8 + q * 2;
                *(float2*)&Cs[row * 132 + col]       = make_float2(c[im][jn][0], c[im][jn][1]);
                *(float2*)&Cs[(row + 8) * 132 + col] = make_float2(c[im][jn][2], c[im][jn][3]);
            }
        __syncthreads();

        const int hb   = n0 >> 7;             // 0..47
        const int type = hb >> 4;             // 0=q,1=k,2=v
        const int h    = hb & 15;
        const int b    = m0 >> 11;
        const int s0   = m0 & 2047;
        const size_t bh = (size_t)(b * HH + h);

        if (type < 2) {
            float* Out = (type == 0) ? Qo : Ko;
            const float scl = (type == 0) ? 0.088388347648318447f : 1.0f;
#pragma unroll
            for (int p = 0; p < 16; p++) {
                int idx = tid + p * 256;
                int row = idx >> 5, col = (idx & 31) * 4;
                int s = s0 + row;
                float4 v = *(float4*)&Cs[row * 132 + col];
                float4 w = *(float4*)&Cs[row * 132 + (col ^ 64)];
                float ov[4];
#pragma unroll
                for (int j = 0; j < 4; j++) {
                    int d = col + j;
                    float2 t = rt[s * 64 + (d & 63)];
                    float val  = (&v.x)[j];
                    float part = (&w.x)[j];
                    float r = (d < 64) ? -part : part;
                    ov[j] = to_tf32((val * t.x + r * t.y) * scl);
                }
                *(float4*)&Out[(bh * SS + s) * DD + col] =
                    make_float4(ov[0], ov[1], ov[2], ov[3]);
            }
        } else {
#pragma unroll
            for (int p = 0; p < 16; p++) {
                int idx = tid + p * 256;
                int d = idx >> 5, ch = idx & 31;
                float* vrow = Vo + (bh * DD + d) * SS + s0;
#pragma unroll
                for (int j = 0; j < 4; j++) {
                    int s = ch + j * 32;
                    vrow[s] = to_tf32(Cs[s * 132 + d]);
                }
            }
        }
    }
}

// ---------------- tf32 round-to-nearest copy -------------------------------
__global__ void round_tf32_k(const float4* __restrict__ in, float4* __restrict__ out, int n4) {
    int i = blockIdx.x * blockDim.x + threadIdx.x;
    if (i >= n4) return;
    out[i] = round4(in[i]);
}

// ---------------- RoPE cos/sin table ---------------------------------------
__global__ void rope_table(float2* __restrict__ rt) {
    int idx = blockIdx.x * blockDim.x + threadIdx.x;   // SS*64
    int i = idx & 63, s = idx >> 6;
    float theta = (float)s * exp2f(-0.20762050593045998f * (float)i);
    float sn, cs;
    sincosf(theta, &sn, &cs);
    rt[idx] = make_float2(cs, sn);
}

// ---------------- Flash attention via mma.sync tf32 + cp.async -------------
#define QP 132                               // pitch (floats) for Qs/Ks
#define PP 68                                // pitch for Vs/Ps
#define ATTN2_SMEM ((128 * QP + 64 * QP + 128 * PP + 128 * PP) * 4)

__global__ __launch_bounds__(256, 1)
void attn_mma(const float* __restrict__ Qg_, const float* __restrict__ Kg_,
              const float* __restrict__ Vt_, float* __restrict__ Y) {
    extern __shared__ float sm[];
    float* Qs = sm;                          // [128][QP]  rows=qrow cols=d
    float* Ks = Qs + 128 * QP;               // [64][QP]   rows=kcol cols=d
    float* Vs = Ks + 64 * QP;                // [128][PP]  rows=d    cols=kcol
    float* Ps = Vs + 128 * PP;               // [128][PP]  rows=qrow cols=kcol

    const int tid  = threadIdx.x;
    const int wid  = tid >> 5;
    const int lane = tid & 31;
    const int qb = gridDim.x - 1 - blockIdx.x;   // heavy tiles first
    const int h  = blockIdx.y;
    const int b  = blockIdx.z;
    const int q0 = qb * 128;

    const size_t bh = (size_t)(b * HH + h);
    const float* Qg = Qg_ + bh * SS * DD;    // [s][d] (scaled, tf32)
    const float* Kg = Kg_ + bh * SS * DD;    // [s][d] (tf32)
    const float* Vg = Vt_ + bh * DD * SS;    // [d][s] (tf32)

    const uint32_t qsb = smem_u32(Qs);
    const uint32_t ksb = smem_u32(Ks);
    const uint32_t vsb = smem_u32(Vs);

    // prologue: async Q tile (group 1), K(0) (group 2), V(0) (group 3)
#pragma unroll
    for (int p = 0; p < 16; p++) {           // Q: 128 rows x 32 chunks
        int c = tid + p * 256;
        int row = c >> 5, ch = c & 31;
        CPA16(qsb + (uint32_t)(row * QP + ch * 4) * 4,
              Qg + (size_t)(q0 + row) * DD + ch * 4);
    }
    CPA_COMMIT();
#pragma unroll
    for (int p = 0; p < 8; p++) {            // K: 64 rows x 32 chunks
        int c = tid + p * 256;
        int row = c >> 5, ch = c & 31;
        CPA16(ksb + (uint32_t)(row * QP + ch * 4) * 4,
              Kg + (size_t)row * DD + ch * 4);
    }
    CPA_COMMIT();
#pragma unroll
    for (int p = 0; p < 8; p++) {            // V: 128 rows x 16 chunks
        int c = tid + p * 256;
        int row = c >> 4, ch = c & 15;
        CPA16(vsb + (uint32_t)(row * PP + ch * 4) * 4,
              Vg + (size_t)row * SS + ch * 4);
    }
    CPA_COMMIT();

    const int sub = lane >> 3, r8 = lane & 7;
    const int g = lane >> 2, qq = lane & 3;
    const uint32_t a_q = qsb + (uint32_t)((wid * 16 + (sub & 1) * 8 + r8) * QP + (sub >> 1) * 4) * 4;
    const uint32_t b_k = ksb + (uint32_t)(((sub >> 1) * 8 + r8) * QP + (sub & 1) * 4) * 4;
    const uint32_t a_p = smem_u32(Ps) + (uint32_t)((wid * 16 + (sub & 1) * 8 + r8) * PP + (sub >> 1) * 4) * 4;
    const uint32_t b_v = vsb + (uint32_t)(((sub >> 1) * 8 + r8) * PP + (sub & 1) * 4) * 4;

    float o[16][4];
#pragma unroll
    for (int i = 0; i < 16; i++)
#pragma unroll
        for (int j = 0; j < 4; j++) o[i][j] = 0.f;
    float m0v = -1e30f, m1v = -1e30f, l0 = 0.f, l1 = 0.f;

    const int nkt = 2 * qb + 2;
    for (int kt = 0; kt < nkt; kt++) {
        const int k0 = kt * 64;
        const bool pf = (kt + 1 < nkt);

        // [A] K(kt) (and Q on kt=0) ready
        CPA_WAIT1();
        __syncthreads();

        // S = Q K^T
        float s[8][4];
#pragma unroll
        for (int i = 0; i < 8; i++)
#pragma unroll
            for (int j = 0; j < 4; j++) s[i][j] = 0.f;
#pragma unroll
        for (int kd = 0; kd < 16; kd++) {
            uint32_t a[4];
            LDSM4(a, a_q + kd * 32);
            uint32_t bf[4][4];
#pragma unroll
            for (int nt = 0; nt < 4; nt++)
                LDSM4(bf[nt], b_k + (uint32_t)(nt * 16 * QP) * 4 + kd * 32);
#pragma unroll
            for (int nt = 0; nt < 4; nt++) {
                MMA_TF32(s[nt * 2],     a, bf[nt][0], bf[nt][1]);
                MMA_TF32(s[nt * 2 + 1], a, bf[nt][2], bf[nt][3]);
            }
        }

        // [B] all warps done reading Ks -> prefetch K(kt+1)
        __syncthreads();
        if (pf) {
            int k1 = k0 + 64;
#pragma unroll
            for (int p = 0; p < 8; p++) {
                int c = tid + p * 256;
                int row = c >> 5, ch = c & 31;
                CPA16(ksb + (uint32_t)(row * QP + ch * 4) * 4,
                      Kg + (size_t)(k1 + row) * DD + ch * 4);
            }
            CPA_COMMIT();
        }

        // causal mask (only last two tiles)
        if (kt >= 2 * qb) {
            int row0 = q0 + wid * 16 + g;
#pragma unroll
            for (int j = 0; j < 8; j++) {
                int c = k0 + j * 8 + qq * 2;
                if (c     > row0)     s[j][0] = -1e30f;
                if (c + 1 > row0)     s[j][1] = -1e30f;
                if (c     > row0 + 8) s[j][2] = -1e30f;
                if (c + 1 > row0 + 8) s[j][3] = -1e30f;
            }
        }

        // online softmax
        float tm0 = -1e30f, tm1 = -1e30f;
#pragma unroll
        for (int j = 0; j < 8; j++) {
            tm0 = fmaxf(tm0, fmaxf(s[j][0], s[j][1]));
            tm1 = fmaxf(tm1, fmaxf(s[j][2], s[j][3]));
        }
        tm0 = fmaxf(tm0, __shfl_xor_sync(0xffffffffu, tm0, 1));
        tm0 = fmaxf(tm0, __shfl_xor_sync(0xffffffffu, tm0, 2));
        tm1 = fmaxf(tm1, __shfl_xor_sync(0xffffffffu, tm1, 1));
        tm1 = fmaxf(tm1, __shfl_xor_sync(0xffffffffu, tm1, 2));
        float mn0 = fmaxf(m0v, tm0), mn1 = fmaxf(m1v, tm1);
        float al0 = __expf(m0v - mn0), al1 = __expf(m1v - mn1);
        m0v = mn0; m1v = mn1;
        float rs0 = 0.f, rs1 = 0.f;
#pragma unroll
        for (int j = 0; j < 8; j++) {
            s[j][0] = __expf(s[j][0] - mn0);
            s[j][1] = __expf(s[j][1] - mn0);
            s[j][2] = __expf(s[j][2] - mn1);
            s[j][3] = __expf(s[j][3] - mn1);
            rs0 += s[j][0] + s[j][1];
            rs1 += s[j][2] + s[j][3];
        }
        rs0 += __shfl_xor_sync(0xffffffffu, rs0, 1);
        rs0 += __shfl_xor_sync(0xffffffffu, rs0, 2);
        rs1 += __shfl_xor_sync(0xffffffffu, rs1, 1);
        rs1 += __shfl_xor_sync(0xffffffffu, rs1, 2);
        l0 = l0 * al0 + rs0;
        l1 = l1 * al1 + rs1;
#pragma unroll
        for (int nt = 0; nt < 16; nt++) {
            o[nt][0] *= al0; o[nt][1] *= al0;
            o[nt][2] *= al1; o[nt][3] *= al1;
        }

        // stage P (warp-private rows), tf32-rounded
        {
            int pr0 = (wid * 16 + g) * PP;
#pragma unroll
            for (int j = 0; j < 8; j++) {
                *(float2*)&Ps[pr0 + j * 8 + qq * 2] =
                    make_float2(to_tf32(s[j][0]), to_tf32(s[j][1]));
                *(float2*)&Ps[pr0 + 8 * PP + j * 8 + qq * 2] =
                    make_float2(to_tf32(s[j][2]), to_tf32(s[j][3]));
            }
        }
        __syncwarp();

        // [C] V(kt) ready (leave K(kt+1) in flight if prefetching)
        if (pf) { CPA_WAIT1(); } else { CPA_WAIT0(); }
        __syncthreads();

        // O += P @ V
#pragma unroll
        for (int jk = 0; jk < 8; jk++) {
            uint32_t a[4];
            LDSM4(a, a_p + jk * 32);
#pragma unroll
            for (int nt = 0; nt < 8; nt++) {
                uint32_t bf[4];
                LDSM4(bf, b_v + (uint32_t)(nt * 16 * PP) * 4 + jk * 32);
                MMA_TF32(o[nt * 2],     a, bf[0], bf[1]);
                MMA_TF32(o[nt * 2 + 1], a, bf[2], bf[3]);
            }
        }

        // [D] all warps done reading Vs -> prefetch V(kt+1)
        __syncthreads();
        if (pf) {
            int k1 = k0 + 64;
#pragma unroll
            for (int p = 0; p < 8; p++) {
                int c = tid + p * 256;
                int row = c >> 4, ch = c & 15;
                CPA16(vsb + (uint32_t)(row * PP + ch * 4) * 4,
                      Vg + (size_t)row * SS + k1 + ch * 4);
            }
            CPA_COMMIT();
        }
    }

    // normalize + tf32-round + write Y [b,s,h,d]
    float i0 = 1.f / l0, i1 = 1.f / l1;
    int row0 = q0 + wid * 16 + g;
    size_t base0 = ((size_t)b * SS + row0) * EE + h * 128;
    size_t base1 = base0 + (size_t)8 * EE;
#pragma unroll
    for (int nt = 0; nt < 16; nt++) {
        int col = nt * 8 + qq * 2;
        *(float2*)&Y[base0 + col] =
            make_float2(to_tf32(o[nt][0] * i0), to_tf32(o[nt][1] * i0));
        *(float2*)&Y[base1 + col] =
            make_float2(to_tf32(o[nt][2] * i1), to_tf32(o[nt][3] * i1));
    }
}

// ---------------- launch -----------------------------------------------------
extern "C" void kernel_launch(void* const* d_in, const int* in_sizes, int n_in,
                              void* d_out, int out_size) {
    const float* x     = (const float*)d_in[0];
    const float* w_qkv = (const float*)d_in[1];
    const float* w_out = (const float*)d_in[2];
    float* out = (float*)d_out;

    float *p_x, *p_wqkv, *p_wout, *p_Q, *p_K, *p_Vt, *p_y;
    float2* p_rope;
    cudaGetSymbolAddress((void**)&p_x,    g_x);
    cudaGetSymbolAddress((void**)&p_wqkv, g_wqkv);
    cudaGetSymbolAddress((void**)&p_wout, g_wout);
    cudaGetSymbolAddress((void**)&p_Q,    g_Q);
    cudaGetSymbolAddress((void**)&p_K,    g_K);
    cudaGetSymbolAddress((void**)&p_Vt,   g_Vt);
    cudaGetSymbolAddress((void**)&p_y,    g_y);
    cudaGetSymbolAddress((void**)&p_rope, g_rope);

    cudaFuncSetAttribute(gemm_k<0>, cudaFuncAttributeMaxDynamicSharedMemorySize, GEMM_SMEM);
    cudaFuncSetAttribute(gemm_k<1>, cudaFuncAttributeMaxDynamicSharedMemorySize, GEMM_SMEM);
    cudaFuncSetAttribute(attn_mma, cudaFuncAttributeMaxDynamicSharedMemorySize, ATTN2_SMEM);

    // 0) round GEMM operands to tf32 (RNA); build rope table
    round_tf32_k<<<(MROWS * EE / 4 + 255) / 256, 256>>>((const float4*)x, (float4*)p_x, MROWS * EE / 4);
    round_tf32_k<<<(QKV_N * EE / 4 + 255) / 256, 256>>>((const float4*)w_qkv, (float4*)p_wqkv, QKV_N * EE / 4);
    round_tf32_k<<<(EE * EE / 4 + 255) / 256, 256>>>((const float4*)w_out, (float4*)p_wout, EE * EE / 4);
    rope_table<<<(SS * 64) / 256, 256>>>(p_rope);

    // 1) fused: qkv GEMM + RoPE(q,k) + V transpose  → g_Q, g_K, g_Vt
    gemm_k<1><<<dim3(QKV_N / 128, MROWS / 128), 256, GEMM_SMEM>>>(
        p_x, p_wqkv, nullptr, p_Q, p_K, p_Vt, p_rope, QKV_N, EE);
    // 2) flash attention (mma.sync tf32, cp.async pipelined)
    attn_mma<<<dim3(SS / 128, HH, BB), 256, ATTN2_SMEM>>>(p_Q, p_K, p_Vt, p_y);
    // 3) out = y @ w_out^T
    gemm_k<0><<<dim3(EE / 128, MROWS / 128), 256, GEMM_SMEM>>>(
        p_y, p_wout, out, nullptr, nullptr, nullptr, nullptr, EE, EE);
}